// round 14
// baseline (speedup 1.0000x reference)
#include <cuda_runtime.h>
#include <cuda_bf16.h>
#include <cstdint>

// ---------------- problem constants ----------------
#define Bc    32
#define Nc    1024
#define Ac    16
#define Ec    4096
#define FINc  16
#define Hc    64
#define MIDc  208          // F_IN + 3*H
#define NODES 32768        // B*N
#define ROWSc 524288       // B*A*N
#define NEDGE 131072       // B*E
#define NFCHUNK 2048       // final chunks (16 nodes each)
#define NSCHUNK 256        // stats chunks (128 nodes each)

// ---------------- scratch (device globals; referenced ONLY from device code) --
__device__ float g_xc[NODES * MIDc];
__device__ float g_np[NODES * MIDc];
__device__ float g_pre1[Bc * Ac * MIDc];
__device__ float g_ewp[MIDc];
__device__ float g_cb[MIDc];
__device__ float g_alpha[MIDc];
__device__ float g_beta[MIDc];
__device__ float g_logits[ROWSc];
// CSR
__device__ int   g_rowptr[NODES + 1];
__device__ int   g_col[NEDGE];
// closed-form BN stats
__device__ float g_D[NODES];
__device__ float g_Da[Bc * Ac];
__device__ float g_sd2p[Bc];
__device__ float g_p2[NSCHUNK * 3 * MIDc];
// per-chunk softmax partials (max, sumexp)
__device__ float g_smx[NFCHUNK * 2];
// W bf16 hi/lo planes, [slice][n][kpair]; K padded 208->256
__device__ unsigned int g_Bh[2 * MIDc * 128];
__device__ unsigned int g_Bl[2 * MIDc * 128];

// ================= CSR + dist sums (one kernel, block = batch) =============
__global__ void __launch_bounds__(1024) k_csrd(const int* __restrict__ links,
                                               const int* __restrict__ loc,
                                               const float* __restrict__ dist) {
    int b = blockIdx.x, t = threadIdx.x;
    __shared__ int cnt[1024];
    __shared__ int sc[1024];
    __shared__ int fil[1024];
    __shared__ int sloc[Ac];
    __shared__ float rsd[32];
    cnt[t] = 0; fil[t] = 0;
    if (t < Ac) sloc[t] = loc[b * Ac + t];
    __syncthreads();
    const int* lb = links + b * 2 * Ec;
    #pragma unroll
    for (int e = t; e < Ec; e += 1024) atomicAdd(&cnt[lb[Ec + e]], 1);
    float D = 0.f, sd2 = 0.f;
    #pragma unroll
    for (int a = 0; a < Ac; a++) {
        float d = dist[(size_t)sloc[a] * Nc + t];
        D += d;
        sd2 = fmaf(d, d, sd2);
    }
    g_D[b * Nc + t] = D;
    __syncthreads();
    sc[t] = cnt[t];
    __syncthreads();
    for (int off = 1; off < 1024; off <<= 1) {
        int x = (t >= off) ? sc[t - off] : 0;
        __syncthreads();
        sc[t] += x;
        __syncthreads();
    }
    int base = sc[t] - cnt[t];
    g_rowptr[b * Nc + t] = b * Ec + base;
    if (b == Bc - 1 && t == 1023) g_rowptr[NODES] = NEDGE;
    __syncthreads();
    cnt[t] = base;
    __syncthreads();
    #pragma unroll
    for (int e = t; e < Ec; e += 1024) {
        int src = lb[e], dst = lb[Ec + e];
        int pos = b * Ec + cnt[dst] + atomicAdd(&fil[dst], 1);
        g_col[pos] = b * Nc + src;
    }
    #pragma unroll
    for (int o = 16; o; o >>= 1) sd2 += __shfl_xor_sync(0xffffffffu, sd2, o);
    if ((t & 31) == 0) rsd[t >> 5] = sd2;
    __syncthreads();
    if (t < 32) {
        float v = rsd[t];
        #pragma unroll
        for (int o = 16; o; o >>= 1) v += __shfl_xor_sync(0xffffffffu, v, o);
        if (t == 0) g_sd2p[b] = v;
    }
    int w = t >> 5, lane = t & 31;
    if (w < Ac) {
        const float* row = dist + (size_t)sloc[w] * Nc;
        float s = 0.f;
        for (int n = lane; n < Nc; n += 32) s += row[n];
        #pragma unroll
        for (int o = 16; o; o >>= 1) s += __shfl_xor_sync(0xffffffffu, s, o);
        if (lane == 0) g_Da[b * Ac + w] = s;
    }
}

// ================= W -> bf16 hi/lo planes, B^T layout [n][kpair] =========
__global__ void k_prepW(const float* __restrict__ W1) {
    int i = blockIdx.x * blockDim.x + threadIdx.x;
    if (i >= 2 * MIDc * 128) return;
    int s = i / (MIDc * 128);
    int rem = i - s * (MIDc * 128);
    int n  = rem >> 7;
    int kp = rem & 127;
    int k0 = 2 * kp;
    float w0 = (k0     < MIDc) ? W1[(size_t)(s * MIDc + k0)     * MIDc + n] : 0.f;
    float w1 = (k0 + 1 < MIDc) ? W1[(size_t)(s * MIDc + k0 + 1) * MIDc + n] : 0.f;
    __nv_bfloat16 h0 = __float2bfloat16(w0), h1 = __float2bfloat16(w1);
    __nv_bfloat16 l0 = __float2bfloat16(w0 - __bfloat162float(h0));
    __nv_bfloat16 l1 = __float2bfloat16(w1 - __bfloat162float(h1));
    g_Bh[i] = (uint32_t)__bfloat16_as_ushort(h0) | ((uint32_t)__bfloat16_as_ushort(h1) << 16);
    g_Bl[i] = (uint32_t)__bfloat16_as_ushort(l0) | ((uint32_t)__bfloat16_as_ushort(l1) << 16);
}

// ====== fused conv (float4 gather, 2-way pipelined + MLP + LN + ReLU) =======
template <int F>
__global__ void __launch_bounds__(512) k_conv(const float* __restrict__ gnodes,
                                              const float* __restrict__ W,
                                              const float* __restrict__ bias,
                                              const float* __restrict__ gg,
                                              const float* __restrict__ beta,
                                              int layer) {
    const float* X;
    int xs, outOff;
    if (layer == 0)      { X = gnodes;    xs = FINc; outOff = 16; }
    else if (layer == 1) { X = g_xc + 16; xs = MIDc; outOff = 80; }
    else                 { X = g_xc + 80; xs = MIDc; outOff = 144; }

    int tid = threadIdx.x;
    int h = tid & 63, tg = tid >> 6;
    int base = blockIdx.x * 32;
    __shared__ float sW[F * 64];
    __shared__ __align__(16) float sagg[32][64];
    __shared__ float sbias[64], sg[64], sb[64];
    __shared__ float red1[8][2][4], red2[8][2][4];
    if (layer == 0) {
        int node = base + (tid >> 4);
        g_xc[(size_t)node * MIDc + (tid & 15)] = gnodes[(size_t)node * FINc + (tid & 15)];
    }
    for (int i = tid; i < F * 64; i += 512) sW[i] = W[i];
    if (tid < 64) { sbias[tid] = bias[tid]; sg[tid] = gg[tid]; sb[tid] = beta[tid]; }
    // ---- float4 gather, 2 independent accumulators (2 loads in flight) ----
    constexpr int NF4 = F / 4;
    constexpr int AGGT = 32 * NF4;
    if (tid < AGGT) {
        int node_slot = tid / NF4;
        int c4 = tid - node_slot * NF4;
        int node = base + node_slot;
        int p0 = g_rowptr[node], p1 = g_rowptr[node + 1];
        float4 s0 = make_float4(0.f, 0.f, 0.f, 0.f);
        float4 s1 = make_float4(0.f, 0.f, 0.f, 0.f);
        int p = p0;
        for (; p + 2 <= p1; p += 2) {
            int c0 = g_col[p], c1 = g_col[p + 1];
            const float4 v0 = *reinterpret_cast<const float4*>(&X[(size_t)c0 * xs + c4 * 4]);
            const float4 v1 = *reinterpret_cast<const float4*>(&X[(size_t)c1 * xs + c4 * 4]);
            s0.x += v0.x; s0.y += v0.y; s0.z += v0.z; s0.w += v0.w;
            s1.x += v1.x; s1.y += v1.y; s1.z += v1.z; s1.w += v1.w;
        }
        if (p < p1) {
            const float4 v = *reinterpret_cast<const float4*>(&X[(size_t)g_col[p] * xs + c4 * 4]);
            s0.x += v.x; s0.y += v.y; s0.z += v.z; s0.w += v.w;
        }
        s0.x += s1.x; s0.y += s1.y; s0.z += s1.z; s0.w += s1.w;
        *reinterpret_cast<float4*>(&sagg[node_slot][c4 * 4]) = s0;
    }
    __syncthreads();
    float acc[4];
    #pragma unroll
    for (int j = 0; j < 4; j++) acc[j] = sbias[h];
    #pragma unroll
    for (int f = 0; f < F; f += 4) {
        float w0 = sW[(f + 0) * 64 + h];
        float w1 = sW[(f + 1) * 64 + h];
        float w2 = sW[(f + 2) * 64 + h];
        float w3 = sW[(f + 3) * 64 + h];
        #pragma unroll
        for (int j = 0; j < 4; j++) {
            float4 a = *reinterpret_cast<const float4*>(&sagg[tg * 4 + j][f]);
            acc[j] = fmaf(a.x, w0, acc[j]);
            acc[j] = fmaf(a.y, w1, acc[j]);
            acc[j] = fmaf(a.z, w2, acc[j]);
            acc[j] = fmaf(a.w, w3, acc[j]);
        }
    }
    float v1[4], v2[4];
    #pragma unroll
    for (int j = 0; j < 4; j++) { v1[j] = acc[j]; v2[j] = acc[j] * acc[j]; }
    #pragma unroll
    for (int o = 16; o; o >>= 1) {
        #pragma unroll
        for (int j = 0; j < 4; j++) {
            v1[j] += __shfl_xor_sync(0xffffffffu, v1[j], o);
            v2[j] += __shfl_xor_sync(0xffffffffu, v2[j], o);
        }
    }
    int wh = h >> 5;
    if ((h & 31) == 0) {
        #pragma unroll
        for (int j = 0; j < 4; j++) { red1[tg][wh][j] = v1[j]; red2[tg][wh][j] = v2[j]; }
    }
    __syncthreads();
    #pragma unroll
    for (int j = 0; j < 4; j++) {
        float sum = red1[tg][0][j] + red1[tg][1][j];
        float sq  = red2[tg][0][j] + red2[tg][1][j];
        float mean = sum * (1.f / 64.f);
        float var  = sq * (1.f / 64.f) - mean * mean;
        float y = (acc[j] - mean) * rsqrtf(var + 1e-5f) * sg[h] + sb[h];
        int node = base + tg * 4 + j;
        g_xc[(size_t)node * MIDc + outOff + h] = fmaxf(y, 0.f);
    }
}

// ========== tensor GEMM via mma.sync bf16 (3-term compensated) ==========
// One launch, 260 CTAs. Blocks 0..3: pre1 (loc-gathered A, slice 0).
// Blocks 4..259: np (A = g_xc, slice 1).  Clean epilogue (no stats fusion).
#define SA_H 0
#define SA_L 16896
#define SB_H 33792
#define SB_L 61248
#define TG_SMEM 88704

__device__ __forceinline__ void mma16816(float* c, uint32_t a0, uint32_t a1,
                                         uint32_t a2, uint32_t a3,
                                         uint32_t b0, uint32_t b1) {
    asm volatile(
        "mma.sync.aligned.m16n8k16.row.col.f32.bf16.bf16.f32 "
        "{%0,%1,%2,%3}, {%4,%5,%6,%7}, {%8,%9}, {%0,%1,%2,%3};"
        : "+f"(c[0]), "+f"(c[1]), "+f"(c[2]), "+f"(c[3])
        : "r"(a0), "r"(a1), "r"(a2), "r"(a3), "r"(b0), "r"(b1));
}

__global__ void __launch_bounds__(256, 1) k_tgemm(const int* __restrict__ loc) {
    bool small = blockIdx.x < 4;
    int slice  = small ? 0 : 1;
    float* C   = small ? g_pre1 : g_np;
    int bm     = (small ? blockIdx.x : (blockIdx.x - 4)) * 128;

    extern __shared__ char smem[];
    uint32_t* sAh = reinterpret_cast<uint32_t*>(smem + SA_H);
    uint32_t* sAl = reinterpret_cast<uint32_t*>(smem + SA_L);
    uint32_t* sBh = reinterpret_cast<uint32_t*>(smem + SB_H);
    uint32_t* sBl = reinterpret_cast<uint32_t*>(smem + SB_L);

    int tid = threadIdx.x;
    int wid = tid >> 5, lane = tid & 31;
    int gid = lane >> 2, tig = lane & 3;
    int m0 = wid * 16;
    const uint32_t* Bh = g_Bh + slice * (MIDc * 128);
    const uint32_t* Bl = g_Bl + slice * (MIDc * 128);

    float acc[26][4];
    #pragma unroll
    for (int j = 0; j < 26; j++)
        #pragma unroll
        for (int q = 0; q < 4; q++) acc[j][q] = 0.f;

    for (int c = 0; c < 4; c++) {
        #pragma unroll
        for (int t = 0; t < 16; t++) {
            int i = tid + t * 256;
            int row = i >> 5, w = i & 31;
            int gk = c * 64 + 2 * w;
            int ar = bm + row;
            size_t abase;
            if (small) {
                int node = (ar >> 4) * Nc + loc[ar];
                abase = (size_t)node * MIDc;
            } else {
                abase = (size_t)ar * MIDc;
            }
            float a0 = 0.f, a1 = 0.f;
            if (gk < MIDc) {
                float2 v = *reinterpret_cast<const float2*>(&g_xc[abase + gk]);
                a0 = v.x; a1 = v.y;
            }
            __nv_bfloat16 h0 = __float2bfloat16(a0), h1 = __float2bfloat16(a1);
            __nv_bfloat16 l0 = __float2bfloat16(a0 - __bfloat162float(h0));
            __nv_bfloat16 l1 = __float2bfloat16(a1 - __bfloat162float(h1));
            sAh[row * 33 + w] = (uint32_t)__bfloat16_as_ushort(h0) | ((uint32_t)__bfloat16_as_ushort(h1) << 16);
            sAl[row * 33 + w] = (uint32_t)__bfloat16_as_ushort(l0) | ((uint32_t)__bfloat16_as_ushort(l1) << 16);
        }
        #pragma unroll
        for (int t = 0; t < 26; t++) {
            int i = tid + t * 256;
            int n = i >> 5, w = i & 31;
            sBh[n * 33 + w] = Bh[n * 128 + c * 32 + w];
            sBl[n * 33 + w] = Bl[n * 128 + c * 32 + w];
        }
        __syncthreads();

        int nks = (c < 3) ? 4 : 1;
        for (int ks = 0; ks < nks; ks++) {
            int kb = ks * 8;
            int ra = (m0 + gid) * 33 + kb + tig;
            uint32_t ah0 = sAh[ra],       ah1 = sAh[ra + 264];
            uint32_t ah2 = sAh[ra + 4],   ah3 = sAh[ra + 268];
            uint32_t al0 = sAl[ra],       al1 = sAl[ra + 264];
            uint32_t al2 = sAl[ra + 4],   al3 = sAl[ra + 268];
            #pragma unroll
            for (int j = 0; j < 26; j++) {
                int rb = (j * 8 + gid) * 33 + kb + tig;
                uint32_t bh0 = sBh[rb], bh1 = sBh[rb + 4];
                uint32_t bl0 = sBl[rb], bl1 = sBl[rb + 4];
                mma16816(acc[j], ah0, ah1, ah2, ah3, bh0, bh1);
                mma16816(acc[j], al0, al1, al2, al3, bh0, bh1);
                mma16816(acc[j], ah0, ah1, ah2, ah3, bl0, bl1);
            }
        }
        __syncthreads();
    }

    int r0 = bm + m0 + gid, r1 = r0 + 8;
    #pragma unroll
    for (int j = 0; j < 26; j++) {
        int n0 = j * 8 + 2 * tig;
        *reinterpret_cast<float2*>(&C[(size_t)r0 * MIDc + n0]) = make_float2(acc[j][0], acc[j][1]);
        *reinterpret_cast<float2*>(&C[(size_t)r1 * MIDc + n0]) = make_float2(acc[j][2], acc[j][3]);
    }
}

// ================= stats sweep over node_proj =================
__global__ void __launch_bounds__(256) k_stats2() {
    int blk = blockIdx.x;
    int base = blk * 128;
    int tid = threadIdx.x;
    __shared__ float sD[128];
    if (tid < 128) sD[tid] = g_D[base + tid];
    __syncthreads();
    if (tid >= MIDc) return;
    int m = tid;
    float s1 = 0.f, s2 = 0.f, sd = 0.f;
    for (int r = 0; r < 128; r++) {
        float u = g_np[(size_t)(base + r) * MIDc + m];
        s1 += u;
        s2 = fmaf(u, u, s2);
        sd = fmaf(u, sD[r], sd);
    }
    g_p2[(size_t)blk * 3 * MIDc + m]            = s1;
    g_p2[(size_t)blk * 3 * MIDc + MIDc + m]     = s2;
    g_p2[(size_t)blk * 3 * MIDc + 2 * MIDc + m] = sd;
}

// ================= closed-form BN reduce (ewp inlined) ======================
__global__ void __launch_bounds__(256) k_reduce2(const float* __restrict__ bn_g,
                                                 const float* __restrict__ bn_b,
                                                 const float* __restrict__ eW,
                                                 const float* __restrict__ eb,
                                                 const float* __restrict__ W1,
                                                 const float* __restrict__ b1) {
    int tid = threadIdx.x;
    __shared__ float sDa[Bc * Ac];
    for (int i = tid; i < Bc * Ac; i += 256) sDa[i] = g_Da[i];
    __syncthreads();
    if (tid >= MIDc) return;
    int m = tid;
    float ef = 0.f, cf = 0.f;
    #pragma unroll 8
    for (int h2 = 0; h2 < Hc; h2++) {
        float w = W1[(size_t)(2 * MIDc + h2) * MIDc + m];
        ef = fmaf(eW[h2], w, ef);
        cf = fmaf(eb[h2], w, cf);
    }
    cf += b1[m];
    g_ewp[m] = ef;
    g_cb[m]  = cf;
    float SD = 0.f, SD2 = 0.f;
    for (int i = 0; i < Bc * Ac; i++) SD += sDa[i];
    for (int b = 0; b < Bc; b++) SD2 += g_sd2p[b];
    double c_ = (double)cf, e = (double)ef;
    float S2np = 0.f, SnpD = 0.f, S2v = 0.f, SvDa = 0.f;
    double S1np = 0.0, S1v = 0.0, cross = 0.0;
    for (int b = 0; b < Bc; b++) {
        float s1b = 0.f;
        for (int c = 0; c < 8; c++) {
            int ch = b * 8 + c;
            s1b  += g_p2[(size_t)ch * 3 * MIDc + m];
            S2np += g_p2[(size_t)ch * 3 * MIDc + MIDc + m];
            SnpD += g_p2[(size_t)ch * 3 * MIDc + 2 * MIDc + m];
        }
        float s1vb = 0.f;
        for (int a = 0; a < Ac; a++) {
            float v = g_pre1[(size_t)(b * Ac + a) * MIDc + m];
            s1vb += v;
            S2v  = fmaf(v, v, S2v);
            SvDa = fmaf(v, sDa[b * Ac + a], SvDa);
        }
        S1np += (double)s1b;
        S1v  += (double)s1vb;
        cross += ((double)s1b + (double)Nc * c_) * (double)s1vb;
    }
    double S1u = S1np + (double)NODES * c_;
    double S2u = (double)S2np + 2.0 * c_ * S1np + (double)NODES * c_ * c_;
    double SuD = (double)SnpD + c_ * (double)SD;
    double s1 = (double)Ac * S1u + (double)Nc * S1v + e * (double)SD;
    double s2 = (double)Ac * S2u + (double)Nc * (double)S2v + e * e * (double)SD2
              + 2.0 * cross + 2.0 * e * SuD + 2.0 * e * (double)SvDa;
    double inv = 1.0 / (double)ROWSc;
    double mu = s1 * inv;
    double var = s2 * inv - mu * mu;
    float al = bn_g[m] * (float)rsqrt(var + 1e-5);
    g_alpha[m] = al;
    g_beta[m]  = bn_b[m] - (float)mu * al;
}

// ====== final logits + per-chunk softmax partials (max, sumexp) =============
__global__ void __launch_bounds__(512) k_final(const int* __restrict__ loc,
                                               const float* __restrict__ dist,
                                               const float* __restrict__ W2,
                                               const float* __restrict__ b2,
                                               const int* __restrict__ mask) {
    int chunk = blockIdx.x;
    int p0 = chunk * 16;
    int b = p0 >> 10;
    int tid = threadIdx.x;
    int a = tid >> 5, lane = tid & 31;
    __shared__ float S[16][224];
    __shared__ float sal[224], sbe[224], scb[224], sewp[224], sw2[224];
    __shared__ float sd[16][Ac];
    __shared__ float slg[256];
    __shared__ float red[16];
    __shared__ int sloc[Ac];
    for (int i = tid; i < 224; i += 512) {
        bool v = i < MIDc;
        sal[i] = v ? g_alpha[i] : 0.f;
        sbe[i] = v ? g_beta[i] : 0.f;
        scb[i] = v ? g_cb[i]   : 0.f;
        sewp[i] = v ? g_ewp[i] : 0.f;
        sw2[i] = v ? W2[i]     : 0.f;
    }
    if (tid < Ac) sloc[tid] = loc[b * Ac + tid];
    __syncthreads();
    for (int i = tid; i < 16 * 224; i += 512) {
        int r = i / 224, c = i - r * 224;
        S[r][c] = (c < MIDc) ? sal[c] * g_np[(size_t)(p0 + r) * MIDc + c] : 0.f;
    }
    for (int i = tid; i < 16 * Ac; i += 512) {
        int r = i >> 4, aa = i & 15;
        int n = (p0 + r) & 1023;
        sd[r][aa] = dist[(size_t)sloc[aa] * Nc + n];
    }
    float P[7], Q[7], Wr[7];
    #pragma unroll
    for (int q = 0; q < 7; q++) {
        int m = q * 32 + lane;
        float al = sal[m];
        float sp = (m < MIDc) ? g_pre1[(size_t)(b * Ac + a) * MIDc + m] : 0.f;
        P[q] = fmaf(al, sp + scb[m], sbe[m]);
        Q[q] = al * sewp[m];
        Wr[q] = sw2[m];
    }
    __syncthreads();
    float bb2 = b2[0];
    for (int ii = 0; ii < 16; ii++) {
        int n = (p0 + ii) & 1023;
        float d = sd[ii][a];
        float part = 0.f;
        #pragma unroll
        for (int q = 0; q < 7; q++) {
            float s = S[ii][q * 32 + lane];
            float arg = fmaf(d, Q[q], s + P[q]);
            part = fmaf(fmaxf(arg, 0.f), Wr[q], part);
        }
        #pragma unroll
        for (int o = 16; o; o >>= 1) part += __shfl_xor_sync(0xffffffffu, part, o);
        if (lane == 0) {
            int ridx = b * (Ac * Nc) + a * Nc + n;
            float lg = (mask[ridx] != 0) ? (part + bb2) : -1e8f;
            g_logits[ridx] = lg;
            slg[a * 16 + ii] = lg;
        }
    }
    __syncthreads();
    if (tid < 256) {
        float v = slg[tid];
        float mx = v;
        #pragma unroll
        for (int o = 16; o; o >>= 1) mx = fmaxf(mx, __shfl_xor_sync(0xffffffffu, mx, o));
        if ((tid & 31) == 0) red[tid >> 5] = mx;
        __syncwarp();
    }
    __syncthreads();
    if (tid < 8) {
        float t = red[tid];
        #pragma unroll
        for (int o = 4; o; o >>= 1) t = fmaxf(t, __shfl_xor_sync(0x000000ffu, t, o));
        if (tid == 0) red[8] = t;
    }
    __syncthreads();
    float bmax = red[8];
    if (tid < 256) {
        float s = expf(slg[tid] - bmax);
        #pragma unroll
        for (int o = 16; o; o >>= 1) s += __shfl_xor_sync(0xffffffffu, s, o);
        if ((tid & 31) == 0) red[tid >> 5] = s;
        __syncwarp();
    }
    __syncthreads();
    if (tid < 8) {
        float t = red[tid];
        #pragma unroll
        for (int o = 4; o; o >>= 1) t += __shfl_xor_sync(0x000000ffu, t, o);
        if (tid == 0) {
            g_smx[chunk * 2]     = bmax;
            g_smx[chunk * 2 + 1] = t;
        }
    }
}

// ============ softmax: combine per-batch chunk partials + normalize =========
__global__ void __launch_bounds__(512) k_smax2(float* __restrict__ out) {
    int slice = blockIdx.x;
    int b = slice >> 3;
    size_t off = (size_t)b * (Ac * Nc) + (slice & 7) * 2048;
    int tid = threadIdx.x;
    __shared__ float sM, sInv;
    __shared__ float red[4];
    if (tid < 64) {
        float m = g_smx[(b * 64 + tid) * 2];
        float mx = m;
        #pragma unroll
        for (int o = 16; o; o >>= 1) mx = fmaxf(mx, __shfl_xor_sync(0xffffffffu, mx, o));
        if ((tid & 31) == 0) red[tid >> 5] = mx;
    }
    __syncthreads();
    float M = fmaxf(red[0], red[1]);
    if (tid < 64) {
        float m = g_smx[(b * 64 + tid) * 2];
        float s = g_smx[(b * 64 + tid) * 2 + 1] * expf(m - M);
        #pragma unroll
        for (int o = 16; o; o >>= 1) s += __shfl_xor_sync(0xffffffffu, s, o);
        if ((tid & 31) == 0) red[2 + (tid >> 5)] = s;
    }
    __syncthreads();
    if (tid == 0) { sM = M; sInv = 1.f / (red[2] + red[3]); }
    __syncthreads();
    float Mv = sM, inv = sInv;
    const float* L = g_logits + off;
    float* O = out + off;
    #pragma unroll
    for (int j = 0; j < 4; j++) {
        int i = tid + j * 512;
        O[i] = expf(L[i] - Mv) * inv;
    }
}

// ---------------- launch ----------------
extern "C" void kernel_launch(void* const* d_in, const int* in_sizes, int n_in,
                              void* d_out, int out_size) {
    const float* gnodes = (const float*)d_in[0];
    const int*   links  = (const int*)d_in[1];
    const int*   loc    = (const int*)d_in[2];
    const int*   mask   = (const int*)d_in[3];
    const float* dist   = (const float*)d_in[4];
    const float* cW[3]  = {(const float*)d_in[5],  (const float*)d_in[9],  (const float*)d_in[13]};
    const float* cb_[3] = {(const float*)d_in[6],  (const float*)d_in[10], (const float*)d_in[14]};
    const float* cg[3]  = {(const float*)d_in[7],  (const float*)d_in[11], (const float*)d_in[15]};
    const float* cbe[3] = {(const float*)d_in[8],  (const float*)d_in[12], (const float*)d_in[16]};
    const float* eW  = (const float*)d_in[17];
    const float* eb  = (const float*)d_in[18];
    const float* W1  = (const float*)d_in[19];
    const float* b1  = (const float*)d_in[20];
    const float* bng = (const float*)d_in[21];
    const float* bnb = (const float*)d_in[22];
    const float* W2  = (const float*)d_in[23];
    const float* b2  = (const float*)d_in[24];
    float* out = (float*)d_out;

    cudaFuncSetAttribute(k_tgemm, cudaFuncAttributeMaxDynamicSharedMemorySize, TG_SMEM);

    // W hi/lo planes (independent; first)
    k_prepW<<<(2 * MIDc * 128 + 255) / 256, 256>>>(W1);

    // CSR + dist sums in one kernel
    k_csrd<<<Bc, 1024>>>(links, loc, dist);

    // fused conv layers (layer 0 also copies x0 into xc)
    k_conv<FINc><<<NODES / 32, 512>>>(gnodes, cW[0], cb_[0], cg[0], cbe[0], 0);
    k_conv<Hc>  <<<NODES / 32, 512>>>(gnodes, cW[1], cb_[1], cg[1], cbe[1], 1);
    k_conv<Hc>  <<<NODES / 32, 512>>>(gnodes, cW[2], cb_[2], cg[2], cbe[2], 2);

    // both GEMMs in one launch (gather fused into agent GEMM)
    k_tgemm<<<4 + NODES / 128, 256, TG_SMEM>>>(loc);

    // BN stats
    k_stats2<<<NSCHUNK, 256>>>();
    k_reduce2<<<1, 256>>>(bng, bnb, eW, eb, W1, b1);

    // final logits (+chunk softmax partials) + combine/normalize
    k_final<<<NFCHUNK, 512>>>(loc, dist, W2, b2, mask);
    k_smax2<<<256, 512>>>(out);
}

// round 15
// speedup vs baseline: 1.4869x; 1.4869x over previous
#include <cuda_runtime.h>
#include <cuda_bf16.h>
#include <cstdint>

// ---------------- problem constants ----------------
#define Bc    32
#define Nc    1024
#define Ac    16
#define Ec    4096
#define FINc  16
#define Hc    64
#define MIDc  208          // F_IN + 3*H
#define NODES 32768        // B*N
#define ROWSc 524288       // B*A*N
#define NEDGE 131072       // B*E
#define NFCHUNK 2048       // final chunks (16 nodes each)
#define NSCHUNK 256        // stats chunks (128 nodes each)

// ---------------- scratch (device globals; referenced ONLY from device code) --
__device__ float g_xc[NODES * MIDc];
__device__ float g_np[NODES * MIDc];
__device__ float g_pre1[Bc * Ac * MIDc];
__device__ float g_ewp[MIDc];
__device__ float g_cb[MIDc];
__device__ float g_alpha[MIDc];
__device__ float g_beta[MIDc];
__device__ float g_logits[ROWSc];
// CSR
__device__ int   g_rowptr[NODES + 1];
__device__ int   g_col[NEDGE];
// closed-form BN stats
__device__ float g_D[NODES];
__device__ float g_Da[Bc * Ac];
__device__ float g_sd2p[Bc];
__device__ float g_p2[NSCHUNK * 3 * MIDc];
// per-chunk softmax partials (max, sumexp)
__device__ float g_smx[NFCHUNK * 2];
// W bf16 hi/lo planes, [slice][n][kpair]; K padded 208->256
__device__ unsigned int g_Bh[2 * MIDc * 128];
__device__ unsigned int g_Bl[2 * MIDc * 128];

// ================= CSR + dist sums (one kernel, block = batch) =============
__global__ void __launch_bounds__(1024) k_csrd(const int* __restrict__ links,
                                               const int* __restrict__ loc,
                                               const float* __restrict__ dist) {
    int b = blockIdx.x, t = threadIdx.x;
    __shared__ int cnt[1024];
    __shared__ int sc[1024];
    __shared__ int fil[1024];
    __shared__ int sloc[Ac];
    __shared__ float rsd[32];
    cnt[t] = 0; fil[t] = 0;
    if (t < Ac) sloc[t] = loc[b * Ac + t];
    __syncthreads();
    const int* lb = links + b * 2 * Ec;
    #pragma unroll
    for (int e = t; e < Ec; e += 1024) atomicAdd(&cnt[lb[Ec + e]], 1);
    float D = 0.f, sd2 = 0.f;
    #pragma unroll
    for (int a = 0; a < Ac; a++) {
        float d = dist[(size_t)sloc[a] * Nc + t];
        D += d;
        sd2 = fmaf(d, d, sd2);
    }
    g_D[b * Nc + t] = D;
    __syncthreads();
    sc[t] = cnt[t];
    __syncthreads();
    for (int off = 1; off < 1024; off <<= 1) {
        int x = (t >= off) ? sc[t - off] : 0;
        __syncthreads();
        sc[t] += x;
        __syncthreads();
    }
    int base = sc[t] - cnt[t];
    g_rowptr[b * Nc + t] = b * Ec + base;
    if (b == Bc - 1 && t == 1023) g_rowptr[NODES] = NEDGE;
    __syncthreads();
    cnt[t] = base;
    __syncthreads();
    #pragma unroll
    for (int e = t; e < Ec; e += 1024) {
        int src = lb[e], dst = lb[Ec + e];
        int pos = b * Ec + cnt[dst] + atomicAdd(&fil[dst], 1);
        g_col[pos] = b * Nc + src;
    }
    #pragma unroll
    for (int o = 16; o; o >>= 1) sd2 += __shfl_xor_sync(0xffffffffu, sd2, o);
    if ((t & 31) == 0) rsd[t >> 5] = sd2;
    __syncthreads();
    if (t < 32) {
        float v = rsd[t];
        #pragma unroll
        for (int o = 16; o; o >>= 1) v += __shfl_xor_sync(0xffffffffu, v, o);
        if (t == 0) g_sd2p[b] = v;
    }
    int w = t >> 5, lane = t & 31;
    if (w < Ac) {
        const float* row = dist + (size_t)sloc[w] * Nc;
        float s = 0.f;
        for (int n = lane; n < Nc; n += 32) s += row[n];
        #pragma unroll
        for (int o = 16; o; o >>= 1) s += __shfl_xor_sync(0xffffffffu, s, o);
        if (lane == 0) g_Da[b * Ac + w] = s;
    }
}

// ================= W -> bf16 hi/lo planes, B^T layout [n][kpair] =========
__global__ void k_prepW(const float* __restrict__ W1) {
    int i = blockIdx.x * blockDim.x + threadIdx.x;
    if (i >= 2 * MIDc * 128) return;
    int s = i / (MIDc * 128);
    int rem = i - s * (MIDc * 128);
    int n  = rem >> 7;
    int kp = rem & 127;
    int k0 = 2 * kp;
    float w0 = (k0     < MIDc) ? W1[(size_t)(s * MIDc + k0)     * MIDc + n] : 0.f;
    float w1 = (k0 + 1 < MIDc) ? W1[(size_t)(s * MIDc + k0 + 1) * MIDc + n] : 0.f;
    __nv_bfloat16 h0 = __float2bfloat16(w0), h1 = __float2bfloat16(w1);
    __nv_bfloat16 l0 = __float2bfloat16(w0 - __bfloat162float(h0));
    __nv_bfloat16 l1 = __float2bfloat16(w1 - __bfloat162float(h1));
    g_Bh[i] = (uint32_t)__bfloat16_as_ushort(h0) | ((uint32_t)__bfloat16_as_ushort(h1) << 16);
    g_Bl[i] = (uint32_t)__bfloat16_as_ushort(l0) | ((uint32_t)__bfloat16_as_ushort(l1) << 16);
}

// ====== fused conv (float4 gather, single accumulator + MLP + LN + ReLU) ====
template <int F>
__global__ void __launch_bounds__(512) k_conv(const float* __restrict__ gnodes,
                                              const float* __restrict__ W,
                                              const float* __restrict__ bias,
                                              const float* __restrict__ gg,
                                              const float* __restrict__ beta,
                                              int layer) {
    const float* X;
    int xs, outOff;
    if (layer == 0)      { X = gnodes;    xs = FINc; outOff = 16; }
    else if (layer == 1) { X = g_xc + 16; xs = MIDc; outOff = 80; }
    else                 { X = g_xc + 80; xs = MIDc; outOff = 144; }

    int tid = threadIdx.x;
    int h = tid & 63, tg = tid >> 6;
    int base = blockIdx.x * 32;
    __shared__ float sW[F * 64];
    __shared__ __align__(16) float sagg[32][64];
    __shared__ float sbias[64], sg[64], sb[64];
    __shared__ float red1[8][2][4], red2[8][2][4];
    if (layer == 0) {
        int node = base + (tid >> 4);
        g_xc[(size_t)node * MIDc + (tid & 15)] = gnodes[(size_t)node * FINc + (tid & 15)];
    }
    for (int i = tid; i < F * 64; i += 512) sW[i] = W[i];
    if (tid < 64) { sbias[tid] = bias[tid]; sg[tid] = gg[tid]; sb[tid] = beta[tid]; }
    // ---- float4 gather: F/4 threads per node (R13 measured-best variant) ----
    constexpr int NF4 = F / 4;
    constexpr int AGGT = 32 * NF4;
    if (tid < AGGT) {
        int node_slot = tid / NF4;
        int c4 = tid - node_slot * NF4;
        int node = base + node_slot;
        int p0 = g_rowptr[node], p1 = g_rowptr[node + 1];
        float4 s = make_float4(0.f, 0.f, 0.f, 0.f);
        for (int p = p0; p < p1; p++) {
            const float4 v = *reinterpret_cast<const float4*>(&X[(size_t)g_col[p] * xs + c4 * 4]);
            s.x += v.x; s.y += v.y; s.z += v.z; s.w += v.w;
        }
        *reinterpret_cast<float4*>(&sagg[node_slot][c4 * 4]) = s;
    }
    __syncthreads();
    float acc[4];
    #pragma unroll
    for (int j = 0; j < 4; j++) acc[j] = sbias[h];
    #pragma unroll
    for (int f = 0; f < F; f += 4) {
        float w0 = sW[(f + 0) * 64 + h];
        float w1 = sW[(f + 1) * 64 + h];
        float w2 = sW[(f + 2) * 64 + h];
        float w3 = sW[(f + 3) * 64 + h];
        #pragma unroll
        for (int j = 0; j < 4; j++) {
            float4 a = *reinterpret_cast<const float4*>(&sagg[tg * 4 + j][f]);
            acc[j] = fmaf(a.x, w0, acc[j]);
            acc[j] = fmaf(a.y, w1, acc[j]);
            acc[j] = fmaf(a.z, w2, acc[j]);
            acc[j] = fmaf(a.w, w3, acc[j]);
        }
    }
    float v1[4], v2[4];
    #pragma unroll
    for (int j = 0; j < 4; j++) { v1[j] = acc[j]; v2[j] = acc[j] * acc[j]; }
    #pragma unroll
    for (int o = 16; o; o >>= 1) {
        #pragma unroll
        for (int j = 0; j < 4; j++) {
            v1[j] += __shfl_xor_sync(0xffffffffu, v1[j], o);
            v2[j] += __shfl_xor_sync(0xffffffffu, v2[j], o);
        }
    }
    int wh = h >> 5;
    if ((h & 31) == 0) {
        #pragma unroll
        for (int j = 0; j < 4; j++) { red1[tg][wh][j] = v1[j]; red2[tg][wh][j] = v2[j]; }
    }
    __syncthreads();
    #pragma unroll
    for (int j = 0; j < 4; j++) {
        float sum = red1[tg][0][j] + red1[tg][1][j];
        float sq  = red2[tg][0][j] + red2[tg][1][j];
        float mean = sum * (1.f / 64.f);
        float var  = sq * (1.f / 64.f) - mean * mean;
        float y = (acc[j] - mean) * rsqrtf(var + 1e-5f) * sg[h] + sb[h];
        int node = base + tg * 4 + j;
        g_xc[(size_t)node * MIDc + outOff + h] = fmaxf(y, 0.f);
    }
}

// ========== tensor GEMM via mma.sync bf16 (3-term compensated) ==========
// One launch, 260 CTAs. Blocks 0..3: pre1 (loc-gathered A, slice 0).
// Blocks 4..259: np (A = g_xc, slice 1).  Clean epilogue (no stats fusion).
#define SA_H 0
#define SA_L 16896
#define SB_H 33792
#define SB_L 61248
#define TG_SMEM 88704

__device__ __forceinline__ void mma16816(float* c, uint32_t a0, uint32_t a1,
                                         uint32_t a2, uint32_t a3,
                                         uint32_t b0, uint32_t b1) {
    asm volatile(
        "mma.sync.aligned.m16n8k16.row.col.f32.bf16.bf16.f32 "
        "{%0,%1,%2,%3}, {%4,%5,%6,%7}, {%8,%9}, {%0,%1,%2,%3};"
        : "+f"(c[0]), "+f"(c[1]), "+f"(c[2]), "+f"(c[3])
        : "r"(a0), "r"(a1), "r"(a2), "r"(a3), "r"(b0), "r"(b1));
}

__global__ void __launch_bounds__(256, 1) k_tgemm(const int* __restrict__ loc) {
    bool small = blockIdx.x < 4;
    int slice  = small ? 0 : 1;
    float* C   = small ? g_pre1 : g_np;
    int bm     = (small ? blockIdx.x : (blockIdx.x - 4)) * 128;

    extern __shared__ char smem[];
    uint32_t* sAh = reinterpret_cast<uint32_t*>(smem + SA_H);
    uint32_t* sAl = reinterpret_cast<uint32_t*>(smem + SA_L);
    uint32_t* sBh = reinterpret_cast<uint32_t*>(smem + SB_H);
    uint32_t* sBl = reinterpret_cast<uint32_t*>(smem + SB_L);

    int tid = threadIdx.x;
    int wid = tid >> 5, lane = tid & 31;
    int gid = lane >> 2, tig = lane & 3;
    int m0 = wid * 16;
    const uint32_t* Bh = g_Bh + slice * (MIDc * 128);
    const uint32_t* Bl = g_Bl + slice * (MIDc * 128);

    float acc[26][4];
    #pragma unroll
    for (int j = 0; j < 26; j++)
        #pragma unroll
        for (int q = 0; q < 4; q++) acc[j][q] = 0.f;

    for (int c = 0; c < 4; c++) {
        #pragma unroll
        for (int t = 0; t < 16; t++) {
            int i = tid + t * 256;
            int row = i >> 5, w = i & 31;
            int gk = c * 64 + 2 * w;
            int ar = bm + row;
            size_t abase;
            if (small) {
                int node = (ar >> 4) * Nc + loc[ar];
                abase = (size_t)node * MIDc;
            } else {
                abase = (size_t)ar * MIDc;
            }
            float a0 = 0.f, a1 = 0.f;
            if (gk < MIDc) {
                float2 v = *reinterpret_cast<const float2*>(&g_xc[abase + gk]);
                a0 = v.x; a1 = v.y;
            }
            __nv_bfloat16 h0 = __float2bfloat16(a0), h1 = __float2bfloat16(a1);
            __nv_bfloat16 l0 = __float2bfloat16(a0 - __bfloat162float(h0));
            __nv_bfloat16 l1 = __float2bfloat16(a1 - __bfloat162float(h1));
            sAh[row * 33 + w] = (uint32_t)__bfloat16_as_ushort(h0) | ((uint32_t)__bfloat16_as_ushort(h1) << 16);
            sAl[row * 33 + w] = (uint32_t)__bfloat16_as_ushort(l0) | ((uint32_t)__bfloat16_as_ushort(l1) << 16);
        }
        #pragma unroll
        for (int t = 0; t < 26; t++) {
            int i = tid + t * 256;
            int n = i >> 5, w = i & 31;
            sBh[n * 33 + w] = Bh[n * 128 + c * 32 + w];
            sBl[n * 33 + w] = Bl[n * 128 + c * 32 + w];
        }
        __syncthreads();

        int nks = (c < 3) ? 4 : 1;
        for (int ks = 0; ks < nks; ks++) {
            int kb = ks * 8;
            int ra = (m0 + gid) * 33 + kb + tig;
            uint32_t ah0 = sAh[ra],       ah1 = sAh[ra + 264];
            uint32_t ah2 = sAh[ra + 4],   ah3 = sAh[ra + 268];
            uint32_t al0 = sAl[ra],       al1 = sAl[ra + 264];
            uint32_t al2 = sAl[ra + 4],   al3 = sAl[ra + 268];
            #pragma unroll
            for (int j = 0; j < 26; j++) {
                int rb = (j * 8 + gid) * 33 + kb + tig;
                uint32_t bh0 = sBh[rb], bh1 = sBh[rb + 4];
                uint32_t bl0 = sBl[rb], bl1 = sBl[rb + 4];
                mma16816(acc[j], ah0, ah1, ah2, ah3, bh0, bh1);
                mma16816(acc[j], al0, al1, al2, al3, bh0, bh1);
                mma16816(acc[j], ah0, ah1, ah2, ah3, bl0, bl1);
            }
        }
        __syncthreads();
    }

    int r0 = bm + m0 + gid, r1 = r0 + 8;
    #pragma unroll
    for (int j = 0; j < 26; j++) {
        int n0 = j * 8 + 2 * tig;
        *reinterpret_cast<float2*>(&C[(size_t)r0 * MIDc + n0]) = make_float2(acc[j][0], acc[j][1]);
        *reinterpret_cast<float2*>(&C[(size_t)r1 * MIDc + n0]) = make_float2(acc[j][2], acc[j][3]);
    }
}

// ================= stats sweep over node_proj =================
__global__ void __launch_bounds__(256) k_stats2() {
    int blk = blockIdx.x;
    int base = blk * 128;
    int tid = threadIdx.x;
    __shared__ float sD[128];
    if (tid < 128) sD[tid] = g_D[base + tid];
    __syncthreads();
    if (tid >= MIDc) return;
    int m = tid;
    float s1 = 0.f, s2 = 0.f, sd = 0.f;
    for (int r = 0; r < 128; r++) {
        float u = g_np[(size_t)(base + r) * MIDc + m];
        s1 += u;
        s2 = fmaf(u, u, s2);
        sd = fmaf(u, sD[r], sd);
    }
    g_p2[(size_t)blk * 3 * MIDc + m]            = s1;
    g_p2[(size_t)blk * 3 * MIDc + MIDc + m]     = s2;
    g_p2[(size_t)blk * 3 * MIDc + 2 * MIDc + m] = sd;
}

// ================= closed-form BN reduce (ewp inlined) ======================
__global__ void __launch_bounds__(256) k_reduce2(const float* __restrict__ bn_g,
                                                 const float* __restrict__ bn_b,
                                                 const float* __restrict__ eW,
                                                 const float* __restrict__ eb,
                                                 const float* __restrict__ W1,
                                                 const float* __restrict__ b1) {
    int tid = threadIdx.x;
    __shared__ float sDa[Bc * Ac];
    for (int i = tid; i < Bc * Ac; i += 256) sDa[i] = g_Da[i];
    __syncthreads();
    if (tid >= MIDc) return;
    int m = tid;
    float ef = 0.f, cf = 0.f;
    #pragma unroll 8
    for (int h2 = 0; h2 < Hc; h2++) {
        float w = W1[(size_t)(2 * MIDc + h2) * MIDc + m];
        ef = fmaf(eW[h2], w, ef);
        cf = fmaf(eb[h2], w, cf);
    }
    cf += b1[m];
    g_ewp[m] = ef;
    g_cb[m]  = cf;
    float SD = 0.f, SD2 = 0.f;
    for (int i = 0; i < Bc * Ac; i++) SD += sDa[i];
    for (int b = 0; b < Bc; b++) SD2 += g_sd2p[b];
    double c_ = (double)cf, e = (double)ef;
    float S2np = 0.f, SnpD = 0.f, S2v = 0.f, SvDa = 0.f;
    double S1np = 0.0, S1v = 0.0, cross = 0.0;
    for (int b = 0; b < Bc; b++) {
        float s1b = 0.f;
        for (int c = 0; c < 8; c++) {
            int ch = b * 8 + c;
            s1b  += g_p2[(size_t)ch * 3 * MIDc + m];
            S2np += g_p2[(size_t)ch * 3 * MIDc + MIDc + m];
            SnpD += g_p2[(size_t)ch * 3 * MIDc + 2 * MIDc + m];
        }
        float s1vb = 0.f;
        for (int a = 0; a < Ac; a++) {
            float v = g_pre1[(size_t)(b * Ac + a) * MIDc + m];
            s1vb += v;
            S2v  = fmaf(v, v, S2v);
            SvDa = fmaf(v, sDa[b * Ac + a], SvDa);
        }
        S1np += (double)s1b;
        S1v  += (double)s1vb;
        cross += ((double)s1b + (double)Nc * c_) * (double)s1vb;
    }
    double S1u = S1np + (double)NODES * c_;
    double S2u = (double)S2np + 2.0 * c_ * S1np + (double)NODES * c_ * c_;
    double SuD = (double)SnpD + c_ * (double)SD;
    double s1 = (double)Ac * S1u + (double)Nc * S1v + e * (double)SD;
    double s2 = (double)Ac * S2u + (double)Nc * (double)S2v + e * e * (double)SD2
              + 2.0 * cross + 2.0 * e * SuD + 2.0 * e * (double)SvDa;
    double inv = 1.0 / (double)ROWSc;
    double mu = s1 * inv;
    double var = s2 * inv - mu * mu;
    float al = bn_g[m] * (float)rsqrt(var + 1e-5);
    g_alpha[m] = al;
    g_beta[m]  = bn_b[m] - (float)mu * al;
}

// ====== final logits + per-chunk softmax partials (max, sumexp) =============
__global__ void __launch_bounds__(512) k_final(const int* __restrict__ loc,
                                               const float* __restrict__ dist,
                                               const float* __restrict__ W2,
                                               const float* __restrict__ b2,
                                               const int* __restrict__ mask) {
    int chunk = blockIdx.x;
    int p0 = chunk * 16;
    int b = p0 >> 10;
    int tid = threadIdx.x;
    int a = tid >> 5, lane = tid & 31;
    __shared__ float S[16][224];
    __shared__ float sal[224], sbe[224], scb[224], sewp[224], sw2[224];
    __shared__ float sd[16][Ac];
    __shared__ float slg[256];
    __shared__ float red[16];
    __shared__ int sloc[Ac];
    for (int i = tid; i < 224; i += 512) {
        bool v = i < MIDc;
        sal[i] = v ? g_alpha[i] : 0.f;
        sbe[i] = v ? g_beta[i] : 0.f;
        scb[i] = v ? g_cb[i]   : 0.f;
        sewp[i] = v ? g_ewp[i] : 0.f;
        sw2[i] = v ? W2[i]     : 0.f;
    }
    if (tid < Ac) sloc[tid] = loc[b * Ac + tid];
    __syncthreads();
    for (int i = tid; i < 16 * 224; i += 512) {
        int r = i / 224, c = i - r * 224;
        S[r][c] = (c < MIDc) ? sal[c] * g_np[(size_t)(p0 + r) * MIDc + c] : 0.f;
    }
    for (int i = tid; i < 16 * Ac; i += 512) {
        int r = i >> 4, aa = i & 15;
        int n = (p0 + r) & 1023;
        sd[r][aa] = dist[(size_t)sloc[aa] * Nc + n];
    }
    float P[7], Q[7], Wr[7];
    #pragma unroll
    for (int q = 0; q < 7; q++) {
        int m = q * 32 + lane;
        float al = sal[m];
        float sp = (m < MIDc) ? g_pre1[(size_t)(b * Ac + a) * MIDc + m] : 0.f;
        P[q] = fmaf(al, sp + scb[m], sbe[m]);
        Q[q] = al * sewp[m];
        Wr[q] = sw2[m];
    }
    __syncthreads();
    float bb2 = b2[0];
    for (int ii = 0; ii < 16; ii++) {
        int n = (p0 + ii) & 1023;
        float d = sd[ii][a];
        float part = 0.f;
        #pragma unroll
        for (int q = 0; q < 7; q++) {
            float s = S[ii][q * 32 + lane];
            float arg = fmaf(d, Q[q], s + P[q]);
            part = fmaf(fmaxf(arg, 0.f), Wr[q], part);
        }
        #pragma unroll
        for (int o = 16; o; o >>= 1) part += __shfl_xor_sync(0xffffffffu, part, o);
        if (lane == 0) {
            int ridx = b * (Ac * Nc) + a * Nc + n;
            float lg = (mask[ridx] != 0) ? (part + bb2) : -1e8f;
            g_logits[ridx] = lg;
            slg[a * 16 + ii] = lg;
        }
    }
    __syncthreads();
    if (tid < 256) {
        float v = slg[tid];
        float mx = v;
        #pragma unroll
        for (int o = 16; o; o >>= 1) mx = fmaxf(mx, __shfl_xor_sync(0xffffffffu, mx, o));
        if ((tid & 31) == 0) red[tid >> 5] = mx;
        __syncwarp();
    }
    __syncthreads();
    if (tid < 8) {
        float t = red[tid];
        #pragma unroll
        for (int o = 4; o; o >>= 1) t = fmaxf(t, __shfl_xor_sync(0x000000ffu, t, o));
        if (tid == 0) red[8] = t;
    }
    __syncthreads();
    float bmax = red[8];
    if (tid < 256) {
        float s = expf(slg[tid] - bmax);
        #pragma unroll
        for (int o = 16; o; o >>= 1) s += __shfl_xor_sync(0xffffffffu, s, o);
        if ((tid & 31) == 0) red[tid >> 5] = s;
        __syncwarp();
    }
    __syncthreads();
    if (tid < 8) {
        float t = red[tid];
        #pragma unroll
        for (int o = 4; o; o >>= 1) t += __shfl_xor_sync(0x000000ffu, t, o);
        if (tid == 0) {
            g_smx[chunk * 2]     = bmax;
            g_smx[chunk * 2 + 1] = t;
        }
    }
}

// ============ softmax: combine per-batch chunk partials + normalize =========
__global__ void __launch_bounds__(512) k_smax2(float* __restrict__ out) {
    int slice = blockIdx.x;
    int b = slice >> 3;
    size_t off = (size_t)b * (Ac * Nc) + (slice & 7) * 2048;
    int tid = threadIdx.x;
    __shared__ float sM, sInv;
    __shared__ float red[4];
    if (tid < 64) {
        float m = g_smx[(b * 64 + tid) * 2];
        float mx = m;
        #pragma unroll
        for (int o = 16; o; o >>= 1) mx = fmaxf(mx, __shfl_xor_sync(0xffffffffu, mx, o));
        if ((tid & 31) == 0) red[tid >> 5] = mx;
    }
    __syncthreads();
    float M = fmaxf(red[0], red[1]);
    if (tid < 64) {
        float m = g_smx[(b * 64 + tid) * 2];
        float s = g_smx[(b * 64 + tid) * 2 + 1] * expf(m - M);
        #pragma unroll
        for (int o = 16; o; o >>= 1) s += __shfl_xor_sync(0xffffffffu, s, o);
        if ((tid & 31) == 0) red[2 + (tid >> 5)] = s;
    }
    __syncthreads();
    if (tid == 0) { sM = M; sInv = 1.f / (red[2] + red[3]); }
    __syncthreads();
    float Mv = sM, inv = sInv;
    const float* L = g_logits + off;
    float* O = out + off;
    #pragma unroll
    for (int j = 0; j < 4; j++) {
        int i = tid + j * 512;
        O[i] = expf(L[i] - Mv) * inv;
    }
}

// ---------------- launch ----------------
extern "C" void kernel_launch(void* const* d_in, const int* in_sizes, int n_in,
                              void* d_out, int out_size) {
    const float* gnodes = (const float*)d_in[0];
    const int*   links  = (const int*)d_in[1];
    const int*   loc    = (const int*)d_in[2];
    const int*   mask   = (const int*)d_in[3];
    const float* dist   = (const float*)d_in[4];
    const float* cW[3]  = {(const float*)d_in[5],  (const float*)d_in[9],  (const float*)d_in[13]};
    const float* cb_[3] = {(const float*)d_in[6],  (const float*)d_in[10], (const float*)d_in[14]};
    const float* cg[3]  = {(const float*)d_in[7],  (const float*)d_in[11], (const float*)d_in[15]};
    const float* cbe[3] = {(const float*)d_in[8],  (const float*)d_in[12], (const float*)d_in[16]};
    const float* eW  = (const float*)d_in[17];
    const float* eb  = (const float*)d_in[18];
    const float* W1  = (const float*)d_in[19];
    const float* b1  = (const float*)d_in[20];
    const float* bng = (const float*)d_in[21];
    const float* bnb = (const float*)d_in[22];
    const float* W2  = (const float*)d_in[23];
    const float* b2  = (const float*)d_in[24];
    float* out = (float*)d_out;

    cudaFuncSetAttribute(k_tgemm, cudaFuncAttributeMaxDynamicSharedMemorySize, TG_SMEM);

    // W hi/lo planes (independent; first)
    k_prepW<<<(2 * MIDc * 128 + 255) / 256, 256>>>(W1);

    // CSR + dist sums in one kernel
    k_csrd<<<Bc, 1024>>>(links, loc, dist);

    // fused conv layers (layer 0 also copies x0 into xc)
    k_conv<FINc><<<NODES / 32, 512>>>(gnodes, cW[0], cb_[0], cg[0], cbe[0], 0);
    k_conv<Hc>  <<<NODES / 32, 512>>>(gnodes, cW[1], cb_[1], cg[1], cbe[1], 1);
    k_conv<Hc>  <<<NODES / 32, 512>>>(gnodes, cW[2], cb_[2], cg[2], cbe[2], 2);

    // both GEMMs in one launch (gather fused into agent GEMM)
    k_tgemm<<<4 + NODES / 128, 256, TG_SMEM>>>(loc);

    // BN stats
    k_stats2<<<NSCHUNK, 256>>>();
    k_reduce2<<<1, 256>>>(bng, bnb, eW, eb, W1, b1);

    // final logits (+chunk softmax partials) + combine/normalize
    k_final<<<NFCHUNK, 512>>>(loc, dist, W2, b2, mask);
    k_smax2<<<256, 512>>>(out);
}